// round 8
// baseline (speedup 1.0000x reference)
#include <cuda_runtime.h>
#include <math.h>
#include <float.h>
#include <stdint.h>

#define N_NODES 50000
#define E_EDGES 800000
#define E_TOT   850000
#define IN_CH   256
#define H1      4
#define C_CH    64
#define HC1     256
#define C2      64
#define NCLS    10
#define NCHUNK  196         // ceil(50000/256)

// ---------------- scratch (device globals; no cudaMalloc allowed) ----------------
__device__ __align__(16) float g_xlr1[(size_t)N_NODES * 512];  // [xl1 | xr1]
__device__ __align__(16) float g_h1  [(size_t)N_NODES * HC1];
__device__ __align__(16) float g_xlr2[(size_t)N_NODES * 128];  // [xl2 | xr2]
__device__ __align__(16) float g_h2  [(size_t)N_NODES * C2];
__device__ __align__(16) float g_Wp1[(size_t)IN_CH * 512];     // [Wl1 | Wr1]
__device__ __align__(16) float g_Wp2[(size_t)HC1 * 128];       // [Wl2 | Wr2]
__device__ int g_rowptr[N_NODES + 1];
__device__ int g_cnt[N_NODES];
__device__ int g_srcs[E_TOT];
__device__ int g_bsum[256];
__device__ int g_boff[256];

// ---------------- f32x2 helpers ----------------
__device__ __forceinline__ unsigned long long pack2(float x, float y) {
    unsigned long long r;
    asm("mov.b64 %0, {%1, %2};" : "=l"(r) : "f"(x), "f"(y));
    return r;
}
__device__ __forceinline__ void unpack2(unsigned long long v, float& x, float& y) {
    asm("mov.b64 {%0, %1}, %2;" : "=f"(x), "=f"(y) : "l"(v));
}
__device__ __forceinline__ void ffma2(unsigned long long& d,
                                      unsigned long long a, unsigned long long b) {
    asm("fma.rn.f32x2 %0, %1, %2, %0;" : "+l"(d) : "l"(a), "l"(b));
}

// ---------------- CSR build ----------------
__global__ void zero_cnt_kernel() {
    int i = blockIdx.x * blockDim.x + threadIdx.x;
    if (i < N_NODES) g_cnt[i] = 0;
}
__global__ void count_kernel(const int* __restrict__ ei) {
    int i = blockIdx.x * blockDim.x + threadIdx.x;
    if (i >= E_TOT) return;
    int dst = (i < E_EDGES) ? ei[E_EDGES + i] : (i - E_EDGES);
    atomicAdd(&g_cnt[dst], 1);
}
__global__ void scan1_kernel() {
    __shared__ int sh[256];
    int t = threadIdx.x;
    int idx = blockIdx.x * 256 + t;
    int v = (idx < N_NODES) ? g_cnt[idx] : 0;
    sh[t] = v; __syncthreads();
    #pragma unroll
    for (int d = 1; d < 256; d <<= 1) {
        int x = (t >= d) ? sh[t - d] : 0;
        __syncthreads(); sh[t] += x; __syncthreads();
    }
    if (idx < N_NODES) g_rowptr[idx + 1] = sh[t];
    if (t == 255) g_bsum[blockIdx.x] = sh[255];
    if (idx == 0) g_rowptr[0] = 0;
}
__global__ void scan2_kernel() {
    __shared__ int sh[256];
    int t = threadIdx.x;
    int v = (t < NCHUNK) ? g_bsum[t] : 0;
    sh[t] = v; __syncthreads();
    #pragma unroll
    for (int d = 1; d < 256; d <<= 1) {
        int x = (t >= d) ? sh[t - d] : 0;
        __syncthreads(); sh[t] += x; __syncthreads();
    }
    g_boff[t] = sh[t] - v;
}
__global__ void scan3_kernel() {
    int idx = blockIdx.x * 256 + threadIdx.x;
    if (idx < N_NODES) g_rowptr[idx + 1] += g_boff[blockIdx.x];
}
__global__ void scatter_kernel(const int* __restrict__ ei) {
    int i = blockIdx.x * blockDim.x + threadIdx.x;
    if (i >= E_TOT) return;
    int src, dst;
    if (i < E_EDGES) { src = ei[i]; dst = ei[E_EDGES + i]; }
    else             { src = dst = i - E_EDGES; }
    int pos = g_rowptr[dst] + atomicAdd(&g_cnt[dst], 1);
    g_srcs[pos] = src;
}

// ---------------- weight packing: Wp[k][0..Nc-1]=Wa[k], [Nc..2Nc-1]=Wb[k] ----------------
__global__ void packw_kernel(const float* __restrict__ Wa, const float* __restrict__ Wb,
                             float* __restrict__ Wp, int K, int Nc) {
    int i = blockIdx.x * blockDim.x + threadIdx.x;
    if (i >= K * Nc) return;
    int k = i / Nc, c = i % Nc;
    Wp[(size_t)k * 2 * Nc + c]      = Wa[i];
    Wp[(size_t)k * 2 * Nc + Nc + c] = Wb[i];
}

// ---------------- fp32x2 GEMM: C[M,N] = A[M,K] @ B[K,N], BM=BN=128, BK=8 ----------------
__global__ void __launch_bounds__(256)
gemm_f32x2_kernel(const float* __restrict__ A, const float* __restrict__ B,
                  float* __restrict__ C, int M, int N, int K)
{
    const int BM = 128, BN = 128, BK = 8;
    __shared__ float As[2][BK][BM + 4];
    __shared__ float Bs[2][BK][BN];

    int tid = threadIdx.x;
    int rowBase = blockIdx.y * BM;
    int colBase = blockIdx.x * BN;

    int aRow = tid >> 1;            // 0..127
    int aCol = (tid & 1) * 4;       // 0 or 4
    int bRow = tid >> 5;            // 0..7
    int bCol = (tid & 31) * 4;      // 0..124
    int tx = tid & 15;              // 0..15
    int ty = tid >> 4;              // 0..15

    // prologue: load tile k0=0
    float4 aReg, bReg;
    {
        int r = rowBase + aRow;
        aReg = (r < M) ? *(const float4*)&A[(size_t)r * K + aCol]
                       : make_float4(0.f, 0.f, 0.f, 0.f);
        bReg = *(const float4*)&B[(size_t)bRow * N + colBase + bCol];
    }
    As[0][aCol + 0][aRow] = aReg.x;
    As[0][aCol + 1][aRow] = aReg.y;
    As[0][aCol + 2][aRow] = aReg.z;
    As[0][aCol + 3][aRow] = aReg.w;
    *(float4*)&Bs[0][bRow][bCol] = bReg;
    __syncthreads();

    unsigned long long acc[8][4];
    #pragma unroll
    for (int i = 0; i < 8; ++i)
        #pragma unroll
        for (int j = 0; j < 4; ++j) acc[i][j] = 0ull;

    int buf = 0;
    for (int k0 = 0; k0 < K; k0 += BK) {
        bool has_next = (k0 + BK < K);
        if (has_next) {
            int r = rowBase + aRow;
            aReg = (r < M) ? *(const float4*)&A[(size_t)r * K + k0 + BK + aCol]
                           : make_float4(0.f, 0.f, 0.f, 0.f);
            bReg = *(const float4*)&B[(size_t)(k0 + BK + bRow) * N + colBase + bCol];
        }
        #pragma unroll
        for (int k = 0; k < BK; ++k) {
            float4 a0 = *(const float4*)&As[buf][k][ty * 8];
            float4 a1 = *(const float4*)&As[buf][k][ty * 8 + 4];
            const unsigned long long* b64 =
                (const unsigned long long*)&Bs[buf][k][tx * 8];
            unsigned long long bb0 = b64[0], bb1 = b64[1], bb2 = b64[2], bb3 = b64[3];
            float av[8] = {a0.x, a0.y, a0.z, a0.w, a1.x, a1.y, a1.z, a1.w};
            #pragma unroll
            for (int i = 0; i < 8; ++i) {
                unsigned long long aa = pack2(av[i], av[i]);
                ffma2(acc[i][0], aa, bb0);
                ffma2(acc[i][1], aa, bb1);
                ffma2(acc[i][2], aa, bb2);
                ffma2(acc[i][3], aa, bb3);
            }
        }
        if (has_next) {
            buf ^= 1;
            As[buf][aCol + 0][aRow] = aReg.x;
            As[buf][aCol + 1][aRow] = aReg.y;
            As[buf][aCol + 2][aRow] = aReg.z;
            As[buf][aCol + 3][aRow] = aReg.w;
            *(float4*)&Bs[buf][bRow][bCol] = bReg;
            __syncthreads();
        }
    }

    #pragma unroll
    for (int i = 0; i < 8; ++i) {
        int r = rowBase + ty * 8 + i;
        if (r >= M) continue;
        float4 o0, o1;
        unpack2(acc[i][0], o0.x, o0.y);
        unpack2(acc[i][1], o0.z, o0.w);
        unpack2(acc[i][2], o1.x, o1.y);
        unpack2(acc[i][3], o1.z, o1.w);
        float* cp = &C[(size_t)r * N + colBase + tx * 8];
        *(float4*)cp = o0;
        *(float4*)(cp + 4) = o1;
    }
}

// ---------------- layer-1 aggregation: warp per node, ALL 4 heads ----------------
// xlr layout: [node][512] = [xl(4h x 64) | xr(4h x 64)]. lane handles 8 channels,
// head = lane>>3; scores reduced within 8-lane groups; online softmax per head.
__global__ void agg1_kernel(const float* __restrict__ xlr, const float* __restrict__ att,
                            const float* __restrict__ bias, float* __restrict__ out)
{
    int node = blockIdx.x * (blockDim.x >> 5) + (threadIdx.x >> 5);
    if (node >= N_NODES) return;
    int lane = threadIdx.x & 31;
    int c0 = lane * 8;

    const float* xrp = xlr + (size_t)node * 512 + 256 + c0;
    float4 x0 = *(const float4*)xrp, x1 = *(const float4*)(xrp + 4);
    float4 t0 = *(const float4*)&att[c0], t1 = *(const float4*)&att[c0 + 4];
    float xrv[8] = {x0.x, x0.y, x0.z, x0.w, x1.x, x1.y, x1.z, x1.w};
    float atv[8] = {t0.x, t0.y, t0.z, t0.w, t1.x, t1.y, t1.z, t1.w};

    float m = -FLT_MAX, s = 0.f;
    float acc[8] = {0.f, 0.f, 0.f, 0.f, 0.f, 0.f, 0.f, 0.f};

    int e0 = g_rowptr[node], e1 = g_rowptr[node + 1];
    for (int e = e0; e < e1; ++e) {
        int src = g_srcs[e];
        const float* vp = xlr + (size_t)src * 512 + c0;
        float4 v0 = *(const float4*)vp, v1 = *(const float4*)(vp + 4);
        float v[8] = {v0.x, v0.y, v0.z, v0.w, v1.x, v1.y, v1.z, v1.w};
        float p = 0.f;
        #pragma unroll
        for (int i = 0; i < 8; ++i) {
            float t = v[i] + xrv[i];
            t = t > 0.f ? t : 0.2f * t;
            p += t * atv[i];
        }
        p += __shfl_xor_sync(0xffffffffu, p, 4);
        p += __shfl_xor_sync(0xffffffffu, p, 2);
        p += __shfl_xor_sync(0xffffffffu, p, 1);

        float nm = fmaxf(m, p);
        float c = __expf(m - nm);
        float w = __expf(p - nm);
        #pragma unroll
        for (int i = 0; i < 8; ++i) acc[i] = acc[i] * c + w * v[i];
        s = s * c + w;
        m = nm;
    }

    float inv = 1.f / s;
    float4 b0 = *(const float4*)&bias[c0], b1 = *(const float4*)&bias[c0 + 4];
    float bv[8] = {b0.x, b0.y, b0.z, b0.w, b1.x, b1.y, b1.z, b1.w};
    float o[8];
    #pragma unroll
    for (int i = 0; i < 8; ++i) o[i] = fmaxf(acc[i] * inv + bv[i], 0.f);
    float* op = out + (size_t)node * HC1 + c0;
    *(float4*)op       = make_float4(o[0], o[1], o[2], o[3]);
    *(float4*)(op + 4) = make_float4(o[4], o[5], o[6], o[7]);
}

// ---------------- layer-2 aggregation: warp per node, 1 head, C=64 ----------------
// xlr2 layout: [node][128] = [xl2(64) | xr2(64)]
__global__ void agg2_kernel(const float* __restrict__ xlr, const float* __restrict__ att,
                            const float* __restrict__ bias, float* __restrict__ out)
{
    int node = blockIdx.x * (blockDim.x >> 5) + (threadIdx.x >> 5);
    if (node >= N_NODES) return;
    int lane = threadIdx.x & 31;
    int c0 = lane * 2;

    float2 xrv = *(const float2*)&xlr[(size_t)node * 128 + 64 + c0];
    float2 atv = *(const float2*)&att[c0];

    float m = -FLT_MAX, s = 0.f, acc0 = 0.f, acc1 = 0.f;
    int e0 = g_rowptr[node], e1 = g_rowptr[node + 1];
    for (int e = e0; e < e1; ++e) {
        int src = g_srcs[e];
        float2 v = *(const float2*)&xlr[(size_t)src * 128 + c0];
        float t0 = v.x + xrv.x; t0 = t0 > 0.f ? t0 : 0.2f * t0;
        float t1 = v.y + xrv.y; t1 = t1 > 0.f ? t1 : 0.2f * t1;
        float p = t0 * atv.x + t1 * atv.y;
        #pragma unroll
        for (int o = 16; o; o >>= 1) p += __shfl_xor_sync(0xffffffffu, p, o);

        float nm = fmaxf(m, p);
        float c = __expf(m - nm);
        float w = __expf(p - nm);
        acc0 = acc0 * c + w * v.x;
        acc1 = acc1 * c + w * v.y;
        s = s * c + w;
        m = nm;
    }

    float inv = 1.f / s;
    float o0 = fmaxf(acc0 * inv + bias[c0],     0.f);
    float o1 = fmaxf(acc1 * inv + bias[c0 + 1], 0.f);
    *(float2*)&out[(size_t)node * C2 + c0] = make_float2(o0, o1);
}

// ---------------- final linear: out[N,10] = h2[N,64] @ Wlin[64,10] + blin ----------------
__global__ void final_kernel(const float* __restrict__ h, const float* __restrict__ W,
                             const float* __restrict__ b, float* __restrict__ out)
{
    __shared__ float Ws[64 * NCLS];
    __shared__ float bs[NCLS];
    int t = threadIdx.x;
    for (int i = t; i < 64 * NCLS; i += blockDim.x) Ws[i] = W[i];
    if (t < NCLS) bs[t] = b[t];
    __syncthreads();

    int row = blockIdx.x * blockDim.x + t;
    if (row >= N_NODES) return;

    float acc[NCLS];
    #pragma unroll
    for (int j = 0; j < NCLS; ++j) acc[j] = bs[j];
    const float* hr = &h[(size_t)row * 64];
    #pragma unroll
    for (int k = 0; k < 64; ++k) {
        float hv = hr[k];
        #pragma unroll
        for (int j = 0; j < NCLS; ++j) acc[j] += hv * Ws[k * NCLS + j];
    }
    #pragma unroll
    for (int j = 0; j < NCLS; ++j) out[(size_t)row * NCLS + j] = acc[j];
}

// ---------------- launch ----------------
static float* sym_f(const void* s) { void* p = nullptr; cudaGetSymbolAddress(&p, s); return (float*)p; }

extern "C" void kernel_launch(void* const* d_in, const int* in_sizes, int n_in,
                              void* d_out, int out_size)
{
    const float* x    = (const float*)d_in[0];
    const int*   ei   = (const int*)  d_in[1];
    const float* Wl1  = (const float*)d_in[2];
    const float* Wr1  = (const float*)d_in[3];
    const float* att1 = (const float*)d_in[4];
    const float* b1   = (const float*)d_in[5];
    const float* Wl2  = (const float*)d_in[6];
    const float* Wr2  = (const float*)d_in[7];
    const float* att2 = (const float*)d_in[8];
    const float* b2   = (const float*)d_in[9];
    const float* Wlin = (const float*)d_in[10];
    const float* blin = (const float*)d_in[11];
    float* out = (float*)d_out;

    float* xlr1 = sym_f(g_xlr1);
    float* h1   = sym_f(g_h1);
    float* xlr2 = sym_f(g_xlr2);
    float* h2   = sym_f(g_h2);
    float* Wp1  = sym_f(g_Wp1);
    float* Wp2  = sym_f(g_Wp2);

    const int EB = (E_TOT + 255) / 256;

    // weight packing (independent of everything else)
    packw_kernel<<<(IN_CH * 256 + 255) / 256, 256>>>(Wl1, Wr1, Wp1, IN_CH, 256);
    packw_kernel<<<(HC1 * 64 + 255) / 256, 256>>>(Wl2, Wr2, Wp2, HC1, 64);

    // CSR build (counts -> scan -> scatter)
    zero_cnt_kernel<<<NCHUNK, 256>>>();
    count_kernel<<<EB, 256>>>(ei);
    scan1_kernel<<<NCHUNK, 256>>>();
    scan2_kernel<<<1, 256>>>();
    scan3_kernel<<<NCHUNK, 256>>>();
    zero_cnt_kernel<<<NCHUNK, 256>>>();
    scatter_kernel<<<EB, 256>>>(ei);

    // Layer 1: one fused transform GEMM (N=512: xl | xr), then aggregation
    dim3 g1(512 / 128, (N_NODES + 127) / 128);
    gemm_f32x2_kernel<<<g1, 256>>>(x, Wp1, xlr1, N_NODES, 512, IN_CH);
    agg1_kernel<<<(N_NODES + 7) / 8, 256>>>(xlr1, att1, b1, h1);

    // Layer 2: one fused transform GEMM (N=128: xl | xr), then aggregation
    dim3 g2(1, (N_NODES + 127) / 128);
    gemm_f32x2_kernel<<<g2, 256>>>(h1, Wp2, xlr2, N_NODES, 128, HC1);
    agg2_kernel<<<(N_NODES + 7) / 8, 256>>>(xlr2, att2, b2, h2);

    // Classifier
    final_kernel<<<NCHUNK, 256>>>(h2, Wlin, blin, out);
}

// round 9
// speedup vs baseline: 1.0005x; 1.0005x over previous
#include <cuda_runtime.h>
#include <math.h>
#include <float.h>
#include <stdint.h>

#define N_NODES 50000
#define E_EDGES 800000
#define E_TOT   850000
#define IN_CH   256
#define H1      4
#define C_CH    64
#define HC1     256
#define C2      64
#define NCLS    10
#define NCHUNK  196         // ceil(50000/256)

// ---------------- scratch (device globals; no cudaMalloc allowed) ----------------
__device__ __align__(16) float g_xlr1[(size_t)N_NODES * 512];  // [xl1 | xr1]
__device__ __align__(16) float g_h1  [(size_t)N_NODES * HC1];
__device__ __align__(16) float g_xlr2[(size_t)N_NODES * 128];  // [xl2 | xr2]
__device__ __align__(16) float g_h2  [(size_t)N_NODES * C2];
__device__ __align__(16) float g_Wp1[(size_t)IN_CH * 512];     // [Wl1 | Wr1]
__device__ __align__(16) float g_Wp2[(size_t)HC1 * 128];       // [Wl2 | Wr2]
__device__ int g_rowptr[N_NODES + 1];
__device__ int g_cnt[N_NODES];
__device__ int g_srcs[E_TOT];
__device__ int g_bsum[256];
__device__ int g_boff[256];

// ---------------- f32x2 helpers ----------------
__device__ __forceinline__ unsigned long long pack2(float x, float y) {
    unsigned long long r;
    asm("mov.b64 %0, {%1, %2};" : "=l"(r) : "f"(x), "f"(y));
    return r;
}
__device__ __forceinline__ void unpack2(unsigned long long v, float& x, float& y) {
    asm("mov.b64 {%0, %1}, %2;" : "=f"(x), "=f"(y) : "l"(v));
}
__device__ __forceinline__ void ffma2(unsigned long long& d,
                                      unsigned long long a, unsigned long long b) {
    asm("fma.rn.f32x2 %0, %1, %2, %0;" : "+l"(d) : "l"(a), "l"(b));
}

// ---------------- CSR build ----------------
__global__ void zero_cnt_kernel() {
    int i = blockIdx.x * blockDim.x + threadIdx.x;
    if (i < N_NODES) g_cnt[i] = 0;
}
__global__ void count_kernel(const int* __restrict__ ei) {
    int i = blockIdx.x * blockDim.x + threadIdx.x;
    if (i >= E_TOT) return;
    int dst = (i < E_EDGES) ? ei[E_EDGES + i] : (i - E_EDGES);
    atomicAdd(&g_cnt[dst], 1);
}
__global__ void scan1_kernel() {
    __shared__ int sh[256];
    int t = threadIdx.x;
    int idx = blockIdx.x * 256 + t;
    int v = (idx < N_NODES) ? g_cnt[idx] : 0;
    sh[t] = v; __syncthreads();
    #pragma unroll
    for (int d = 1; d < 256; d <<= 1) {
        int x = (t >= d) ? sh[t - d] : 0;
        __syncthreads(); sh[t] += x; __syncthreads();
    }
    if (idx < N_NODES) g_rowptr[idx + 1] = sh[t];
    if (t == 255) g_bsum[blockIdx.x] = sh[255];
    if (idx == 0) g_rowptr[0] = 0;
}
__global__ void scan2_kernel() {
    __shared__ int sh[256];
    int t = threadIdx.x;
    int v = (t < NCHUNK) ? g_bsum[t] : 0;
    sh[t] = v; __syncthreads();
    #pragma unroll
    for (int d = 1; d < 256; d <<= 1) {
        int x = (t >= d) ? sh[t - d] : 0;
        __syncthreads(); sh[t] += x; __syncthreads();
    }
    g_boff[t] = sh[t] - v;
}
__global__ void scan3_kernel() {
    int idx = blockIdx.x * 256 + threadIdx.x;
    if (idx < N_NODES) g_rowptr[idx + 1] += g_boff[blockIdx.x];
}
__global__ void scatter_kernel(const int* __restrict__ ei) {
    int i = blockIdx.x * blockDim.x + threadIdx.x;
    if (i >= E_TOT) return;
    int src, dst;
    if (i < E_EDGES) { src = ei[i]; dst = ei[E_EDGES + i]; }
    else             { src = dst = i - E_EDGES; }
    int pos = g_rowptr[dst] + atomicAdd(&g_cnt[dst], 1);
    g_srcs[pos] = src;
}

// ---------------- weight packing: Wp[k][0..Nc-1]=Wa[k], [Nc..2Nc-1]=Wb[k] ----------------
__global__ void packw_kernel(const float* __restrict__ Wa, const float* __restrict__ Wb,
                             float* __restrict__ Wp, int K, int Nc) {
    int i = blockIdx.x * blockDim.x + threadIdx.x;
    if (i >= K * Nc) return;
    int k = i / Nc, c = i % Nc;
    Wp[(size_t)k * 2 * Nc + c]      = Wa[i];
    Wp[(size_t)k * 2 * Nc + Nc + c] = Wb[i];
}

// ---------------- fp32x2 GEMM: C[M,N] = A[M,K] @ B[K,N], BM=BN=128, BK=8 ----------------
__global__ void __launch_bounds__(256)
gemm_f32x2_kernel(const float* __restrict__ A, const float* __restrict__ B,
                  float* __restrict__ C, int M, int N, int K)
{
    const int BM = 128, BN = 128, BK = 8;
    __shared__ float As[2][BK][BM + 4];
    __shared__ float Bs[2][BK][BN];

    int tid = threadIdx.x;
    int rowBase = blockIdx.y * BM;
    int colBase = blockIdx.x * BN;

    int aRow = tid >> 1;            // 0..127
    int aCol = (tid & 1) * 4;       // 0 or 4
    int bRow = tid >> 5;            // 0..7
    int bCol = (tid & 31) * 4;      // 0..124
    int tx = tid & 15;              // 0..15
    int ty = tid >> 4;              // 0..15

    // prologue: load tile k0=0
    float4 aReg, bReg;
    {
        int r = rowBase + aRow;
        aReg = (r < M) ? *(const float4*)&A[(size_t)r * K + aCol]
                       : make_float4(0.f, 0.f, 0.f, 0.f);
        bReg = *(const float4*)&B[(size_t)bRow * N + colBase + bCol];
    }
    As[0][aCol + 0][aRow] = aReg.x;
    As[0][aCol + 1][aRow] = aReg.y;
    As[0][aCol + 2][aRow] = aReg.z;
    As[0][aCol + 3][aRow] = aReg.w;
    *(float4*)&Bs[0][bRow][bCol] = bReg;
    __syncthreads();

    unsigned long long acc[8][4];
    #pragma unroll
    for (int i = 0; i < 8; ++i)
        #pragma unroll
        for (int j = 0; j < 4; ++j) acc[i][j] = 0ull;

    int buf = 0;
    for (int k0 = 0; k0 < K; k0 += BK) {
        bool has_next = (k0 + BK < K);
        if (has_next) {
            int r = rowBase + aRow;
            aReg = (r < M) ? *(const float4*)&A[(size_t)r * K + k0 + BK + aCol]
                           : make_float4(0.f, 0.f, 0.f, 0.f);
            bReg = *(const float4*)&B[(size_t)(k0 + BK + bRow) * N + colBase + bCol];
        }
        #pragma unroll
        for (int k = 0; k < BK; ++k) {
            float4 a0 = *(const float4*)&As[buf][k][ty * 8];
            float4 a1 = *(const float4*)&As[buf][k][ty * 8 + 4];
            const unsigned long long* b64 =
                (const unsigned long long*)&Bs[buf][k][tx * 8];
            unsigned long long bb0 = b64[0], bb1 = b64[1], bb2 = b64[2], bb3 = b64[3];
            float av[8] = {a0.x, a0.y, a0.z, a0.w, a1.x, a1.y, a1.z, a1.w};
            #pragma unroll
            for (int i = 0; i < 8; ++i) {
                unsigned long long aa = pack2(av[i], av[i]);
                ffma2(acc[i][0], aa, bb0);
                ffma2(acc[i][1], aa, bb1);
                ffma2(acc[i][2], aa, bb2);
                ffma2(acc[i][3], aa, bb3);
            }
        }
        if (has_next) {
            buf ^= 1;
            As[buf][aCol + 0][aRow] = aReg.x;
            As[buf][aCol + 1][aRow] = aReg.y;
            As[buf][aCol + 2][aRow] = aReg.z;
            As[buf][aCol + 3][aRow] = aReg.w;
            *(float4*)&Bs[buf][bRow][bCol] = bReg;
            __syncthreads();
        }
    }

    #pragma unroll
    for (int i = 0; i < 8; ++i) {
        int r = rowBase + ty * 8 + i;
        if (r >= M) continue;
        float4 o0, o1;
        unpack2(acc[i][0], o0.x, o0.y);
        unpack2(acc[i][1], o0.z, o0.w);
        unpack2(acc[i][2], o1.x, o1.y);
        unpack2(acc[i][3], o1.z, o1.w);
        float* cp = &C[(size_t)r * N + colBase + tx * 8];
        *(float4*)cp = o0;
        *(float4*)(cp + 4) = o1;
    }
}

// ---------------- layer-1 aggregation: warp per node, ALL 4 heads ----------------
// xlr layout: [node][512] = [xl(4h x 64) | xr(4h x 64)]. lane handles 8 channels,
// head = lane>>3; scores reduced within 8-lane groups; online softmax per head.
__global__ void agg1_kernel(const float* __restrict__ xlr, const float* __restrict__ att,
                            const float* __restrict__ bias, float* __restrict__ out)
{
    int node = blockIdx.x * (blockDim.x >> 5) + (threadIdx.x >> 5);
    if (node >= N_NODES) return;
    int lane = threadIdx.x & 31;
    int c0 = lane * 8;

    const float* xrp = xlr + (size_t)node * 512 + 256 + c0;
    float4 x0 = *(const float4*)xrp, x1 = *(const float4*)(xrp + 4);
    float4 t0 = *(const float4*)&att[c0], t1 = *(const float4*)&att[c0 + 4];
    float xrv[8] = {x0.x, x0.y, x0.z, x0.w, x1.x, x1.y, x1.z, x1.w};
    float atv[8] = {t0.x, t0.y, t0.z, t0.w, t1.x, t1.y, t1.z, t1.w};

    float m = -FLT_MAX, s = 0.f;
    float acc[8] = {0.f, 0.f, 0.f, 0.f, 0.f, 0.f, 0.f, 0.f};

    int e0 = g_rowptr[node], e1 = g_rowptr[node + 1];
    for (int e = e0; e < e1; ++e) {
        int src = g_srcs[e];
        const float* vp = xlr + (size_t)src * 512 + c0;
        float4 v0 = *(const float4*)vp, v1 = *(const float4*)(vp + 4);
        float v[8] = {v0.x, v0.y, v0.z, v0.w, v1.x, v1.y, v1.z, v1.w};
        float p = 0.f;
        #pragma unroll
        for (int i = 0; i < 8; ++i) {
            float t = v[i] + xrv[i];
            t = t > 0.f ? t : 0.2f * t;
            p += t * atv[i];
        }
        p += __shfl_xor_sync(0xffffffffu, p, 4);
        p += __shfl_xor_sync(0xffffffffu, p, 2);
        p += __shfl_xor_sync(0xffffffffu, p, 1);

        float nm = fmaxf(m, p);
        float c = __expf(m - nm);
        float w = __expf(p - nm);
        #pragma unroll
        for (int i = 0; i < 8; ++i) acc[i] = acc[i] * c + w * v[i];
        s = s * c + w;
        m = nm;
    }

    float inv = 1.f / s;
    float4 b0 = *(const float4*)&bias[c0], b1 = *(const float4*)&bias[c0 + 4];
    float bv[8] = {b0.x, b0.y, b0.z, b0.w, b1.x, b1.y, b1.z, b1.w};
    float o[8];
    #pragma unroll
    for (int i = 0; i < 8; ++i) o[i] = fmaxf(acc[i] * inv + bv[i], 0.f);
    float* op = out + (size_t)node * HC1 + c0;
    *(float4*)op       = make_float4(o[0], o[1], o[2], o[3]);
    *(float4*)(op + 4) = make_float4(o[4], o[5], o[6], o[7]);
}

// ---------------- layer-2 aggregation: warp per node, 1 head, C=64 ----------------
// xlr2 layout: [node][128] = [xl2(64) | xr2(64)]
__global__ void agg2_kernel(const float* __restrict__ xlr, const float* __restrict__ att,
                            const float* __restrict__ bias, float* __restrict__ out)
{
    int node = blockIdx.x * (blockDim.x >> 5) + (threadIdx.x >> 5);
    if (node >= N_NODES) return;
    int lane = threadIdx.x & 31;
    int c0 = lane * 2;

    float2 xrv = *(const float2*)&xlr[(size_t)node * 128 + 64 + c0];
    float2 atv = *(const float2*)&att[c0];

    float m = -FLT_MAX, s = 0.f, acc0 = 0.f, acc1 = 0.f;
    int e0 = g_rowptr[node], e1 = g_rowptr[node + 1];
    for (int e = e0; e < e1; ++e) {
        int src = g_srcs[e];
        float2 v = *(const float2*)&xlr[(size_t)src * 128 + c0];
        float t0 = v.x + xrv.x; t0 = t0 > 0.f ? t0 : 0.2f * t0;
        float t1 = v.y + xrv.y; t1 = t1 > 0.f ? t1 : 0.2f * t1;
        float p = t0 * atv.x + t1 * atv.y;
        #pragma unroll
        for (int o = 16; o; o >>= 1) p += __shfl_xor_sync(0xffffffffu, p, o);

        float nm = fmaxf(m, p);
        float c = __expf(m - nm);
        float w = __expf(p - nm);
        acc0 = acc0 * c + w * v.x;
        acc1 = acc1 * c + w * v.y;
        s = s * c + w;
        m = nm;
    }

    float inv = 1.f / s;
    float o0 = fmaxf(acc0 * inv + bias[c0],     0.f);
    float o1 = fmaxf(acc1 * inv + bias[c0 + 1], 0.f);
    *(float2*)&out[(size_t)node * C2 + c0] = make_float2(o0, o1);
}

// ---------------- final linear: out[N,10] = h2[N,64] @ Wlin[64,10] + blin ----------------
__global__ void final_kernel(const float* __restrict__ h, const float* __restrict__ W,
                             const float* __restrict__ b, float* __restrict__ out)
{
    __shared__ float Ws[64 * NCLS];
    __shared__ float bs[NCLS];
    int t = threadIdx.x;
    for (int i = t; i < 64 * NCLS; i += blockDim.x) Ws[i] = W[i];
    if (t < NCLS) bs[t] = b[t];
    __syncthreads();

    int row = blockIdx.x * blockDim.x + t;
    if (row >= N_NODES) return;

    float acc[NCLS];
    #pragma unroll
    for (int j = 0; j < NCLS; ++j) acc[j] = bs[j];
    const float* hr = &h[(size_t)row * 64];
    #pragma unroll
    for (int k = 0; k < 64; ++k) {
        float hv = hr[k];
        #pragma unroll
        for (int j = 0; j < NCLS; ++j) acc[j] += hv * Ws[k * NCLS + j];
    }
    #pragma unroll
    for (int j = 0; j < NCLS; ++j) out[(size_t)row * NCLS + j] = acc[j];
}

// ---------------- launch ----------------
static float* sym_f(const void* s) { void* p = nullptr; cudaGetSymbolAddress(&p, s); return (float*)p; }

extern "C" void kernel_launch(void* const* d_in, const int* in_sizes, int n_in,
                              void* d_out, int out_size)
{
    const float* x    = (const float*)d_in[0];
    const int*   ei   = (const int*)  d_in[1];
    const float* Wl1  = (const float*)d_in[2];
    const float* Wr1  = (const float*)d_in[3];
    const float* att1 = (const float*)d_in[4];
    const float* b1   = (const float*)d_in[5];
    const float* Wl2  = (const float*)d_in[6];
    const float* Wr2  = (const float*)d_in[7];
    const float* att2 = (const float*)d_in[8];
    const float* b2   = (const float*)d_in[9];
    const float* Wlin = (const float*)d_in[10];
    const float* blin = (const float*)d_in[11];
    float* out = (float*)d_out;

    float* xlr1 = sym_f(g_xlr1);
    float* h1   = sym_f(g_h1);
    float* xlr2 = sym_f(g_xlr2);
    float* h2   = sym_f(g_h2);
    float* Wp1  = sym_f(g_Wp1);
    float* Wp2  = sym_f(g_Wp2);

    const int EB = (E_TOT + 255) / 256;

    // weight packing (independent of everything else)
    packw_kernel<<<(IN_CH * 256 + 255) / 256, 256>>>(Wl1, Wr1, Wp1, IN_CH, 256);
    packw_kernel<<<(HC1 * 64 + 255) / 256, 256>>>(Wl2, Wr2, Wp2, HC1, 64);

    // CSR build (counts -> scan -> scatter)
    zero_cnt_kernel<<<NCHUNK, 256>>>();
    count_kernel<<<EB, 256>>>(ei);
    scan1_kernel<<<NCHUNK, 256>>>();
    scan2_kernel<<<1, 256>>>();
    scan3_kernel<<<NCHUNK, 256>>>();
    zero_cnt_kernel<<<NCHUNK, 256>>>();
    scatter_kernel<<<EB, 256>>>(ei);

    // Layer 1: one fused transform GEMM (N=512: xl | xr), then aggregation
    dim3 g1(512 / 128, (N_NODES + 127) / 128);
    gemm_f32x2_kernel<<<g1, 256>>>(x, Wp1, xlr1, N_NODES, 512, IN_CH);
    agg1_kernel<<<(N_NODES + 7) / 8, 256>>>(xlr1, att1, b1, h1);

    // Layer 2: one fused transform GEMM (N=128: xl | xr), then aggregation
    dim3 g2(1, (N_NODES + 127) / 128);
    gemm_f32x2_kernel<<<g2, 256>>>(h1, Wp2, xlr2, N_NODES, 128, HC1);
    agg2_kernel<<<(N_NODES + 7) / 8, 256>>>(xlr2, att2, b2, h2);

    // Classifier
    final_kernel<<<NCHUNK, 256>>>(h2, Wlin, blin, out);
}

// round 10
// speedup vs baseline: 1.0030x; 1.0025x over previous
#include <cuda_runtime.h>
#include <math.h>
#include <float.h>
#include <stdint.h>

#define N_NODES 50000
#define E_EDGES 800000
#define E_TOT   850000
#define IN_CH   256
#define H1      4
#define C_CH    64
#define HC1     256
#define C2      64
#define NCLS    10
#define NCHUNK  196         // ceil(50000/256)

// ---------------- scratch (device globals; no cudaMalloc allowed) ----------------
__device__ __align__(16) float g_xlr1[(size_t)N_NODES * 512];  // [xl1 | xr1]
__device__ __align__(16) float g_h1  [(size_t)N_NODES * HC1];
__device__ __align__(16) float g_xlr2[(size_t)N_NODES * 128];  // [xl2 | xr2]
__device__ __align__(16) float g_h2  [(size_t)N_NODES * C2];
__device__ __align__(16) float g_Wp1[(size_t)IN_CH * 512];     // [Wl1 | Wr1]
__device__ __align__(16) float g_Wp2[(size_t)HC1 * 128];       // [Wl2 | Wr2]
__device__ int g_rowptr[N_NODES + 1];
__device__ int g_cnt[N_NODES];
__device__ int g_srcs[E_TOT];
__device__ int g_bsum[256];
__device__ int g_boff[256];

// ---------------- f32x2 helpers ----------------
__device__ __forceinline__ unsigned long long pack2(float x, float y) {
    unsigned long long r;
    asm("mov.b64 %0, {%1, %2};" : "=l"(r) : "f"(x), "f"(y));
    return r;
}
__device__ __forceinline__ void unpack2(unsigned long long v, float& x, float& y) {
    asm("mov.b64 {%0, %1}, %2;" : "=f"(x), "=f"(y) : "l"(v));
}
__device__ __forceinline__ void ffma2(unsigned long long& d,
                                      unsigned long long a, unsigned long long b) {
    asm("fma.rn.f32x2 %0, %1, %2, %0;" : "+l"(d) : "l"(a), "l"(b));
}

// ---------------- CSR build ----------------
__global__ void zero_cnt_kernel() {
    int i = blockIdx.x * blockDim.x + threadIdx.x;
    if (i < N_NODES) g_cnt[i] = 0;
}
__global__ void count_kernel(const int* __restrict__ ei) {
    int i = blockIdx.x * blockDim.x + threadIdx.x;
    if (i >= E_TOT) return;
    int dst = (i < E_EDGES) ? ei[E_EDGES + i] : (i - E_EDGES);
    atomicAdd(&g_cnt[dst], 1);
}
__global__ void scan1_kernel() {
    __shared__ int sh[256];
    int t = threadIdx.x;
    int idx = blockIdx.x * 256 + t;
    int v = (idx < N_NODES) ? g_cnt[idx] : 0;
    sh[t] = v; __syncthreads();
    #pragma unroll
    for (int d = 1; d < 256; d <<= 1) {
        int x = (t >= d) ? sh[t - d] : 0;
        __syncthreads(); sh[t] += x; __syncthreads();
    }
    if (idx < N_NODES) g_rowptr[idx + 1] = sh[t];
    if (t == 255) g_bsum[blockIdx.x] = sh[255];
    if (idx == 0) g_rowptr[0] = 0;
}
__global__ void scan2_kernel() {
    __shared__ int sh[256];
    int t = threadIdx.x;
    int v = (t < NCHUNK) ? g_bsum[t] : 0;
    sh[t] = v; __syncthreads();
    #pragma unroll
    for (int d = 1; d < 256; d <<= 1) {
        int x = (t >= d) ? sh[t - d] : 0;
        __syncthreads(); sh[t] += x; __syncthreads();
    }
    g_boff[t] = sh[t] - v;
}
__global__ void scan3_kernel() {
    int idx = blockIdx.x * 256 + threadIdx.x;
    if (idx < N_NODES) g_rowptr[idx + 1] += g_boff[blockIdx.x];
}
__global__ void scatter_kernel(const int* __restrict__ ei) {
    int i = blockIdx.x * blockDim.x + threadIdx.x;
    if (i >= E_TOT) return;
    int src, dst;
    if (i < E_EDGES) { src = ei[i]; dst = ei[E_EDGES + i]; }
    else             { src = dst = i - E_EDGES; }
    int pos = g_rowptr[dst] + atomicAdd(&g_cnt[dst], 1);
    g_srcs[pos] = src;
}

// ---------------- weight packing: Wp[k][0..Nc-1]=Wa[k], [Nc..2Nc-1]=Wb[k] ----------------
__global__ void packw_kernel(const float* __restrict__ Wa, const float* __restrict__ Wb,
                             float* __restrict__ Wp, int K, int Nc) {
    int i = blockIdx.x * blockDim.x + threadIdx.x;
    if (i >= K * Nc) return;
    int k = i / Nc, c = i % Nc;
    Wp[(size_t)k * 2 * Nc + c]      = Wa[i];
    Wp[(size_t)k * 2 * Nc + Nc + c] = Wb[i];
}

// ---------------- fp32x2 GEMM: C[M,N] = A[M,K] @ B[K,N], BM=BN=128, BK=8 ----------------
__global__ void __launch_bounds__(256)
gemm_f32x2_kernel(const float* __restrict__ A, const float* __restrict__ B,
                  float* __restrict__ C, int M, int N, int K)
{
    const int BM = 128, BN = 128, BK = 8;
    __shared__ float As[2][BK][BM + 4];
    __shared__ float Bs[2][BK][BN];

    int tid = threadIdx.x;
    int rowBase = blockIdx.y * BM;
    int colBase = blockIdx.x * BN;

    int aRow = tid >> 1;            // 0..127
    int aCol = (tid & 1) * 4;       // 0 or 4
    int bRow = tid >> 5;            // 0..7
    int bCol = (tid & 31) * 4;      // 0..124
    int tx = tid & 15;              // 0..15
    int ty = tid >> 4;              // 0..15

    // prologue: load tile k0=0
    float4 aReg, bReg;
    {
        int r = rowBase + aRow;
        aReg = (r < M) ? *(const float4*)&A[(size_t)r * K + aCol]
                       : make_float4(0.f, 0.f, 0.f, 0.f);
        bReg = *(const float4*)&B[(size_t)bRow * N + colBase + bCol];
    }
    As[0][aCol + 0][aRow] = aReg.x;
    As[0][aCol + 1][aRow] = aReg.y;
    As[0][aCol + 2][aRow] = aReg.z;
    As[0][aCol + 3][aRow] = aReg.w;
    *(float4*)&Bs[0][bRow][bCol] = bReg;
    __syncthreads();

    unsigned long long acc[8][4];
    #pragma unroll
    for (int i = 0; i < 8; ++i)
        #pragma unroll
        for (int j = 0; j < 4; ++j) acc[i][j] = 0ull;

    int buf = 0;
    for (int k0 = 0; k0 < K; k0 += BK) {
        bool has_next = (k0 + BK < K);
        if (has_next) {
            int r = rowBase + aRow;
            aReg = (r < M) ? *(const float4*)&A[(size_t)r * K + k0 + BK + aCol]
                           : make_float4(0.f, 0.f, 0.f, 0.f);
            bReg = *(const float4*)&B[(size_t)(k0 + BK + bRow) * N + colBase + bCol];
        }
        #pragma unroll
        for (int k = 0; k < BK; ++k) {
            float4 a0 = *(const float4*)&As[buf][k][ty * 8];
            float4 a1 = *(const float4*)&As[buf][k][ty * 8 + 4];
            const unsigned long long* b64 =
                (const unsigned long long*)&Bs[buf][k][tx * 8];
            unsigned long long bb0 = b64[0], bb1 = b64[1], bb2 = b64[2], bb3 = b64[3];
            float av[8] = {a0.x, a0.y, a0.z, a0.w, a1.x, a1.y, a1.z, a1.w};
            #pragma unroll
            for (int i = 0; i < 8; ++i) {
                unsigned long long aa = pack2(av[i], av[i]);
                ffma2(acc[i][0], aa, bb0);
                ffma2(acc[i][1], aa, bb1);
                ffma2(acc[i][2], aa, bb2);
                ffma2(acc[i][3], aa, bb3);
            }
        }
        if (has_next) {
            buf ^= 1;
            As[buf][aCol + 0][aRow] = aReg.x;
            As[buf][aCol + 1][aRow] = aReg.y;
            As[buf][aCol + 2][aRow] = aReg.z;
            As[buf][aCol + 3][aRow] = aReg.w;
            *(float4*)&Bs[buf][bRow][bCol] = bReg;
            __syncthreads();
        }
    }

    #pragma unroll
    for (int i = 0; i < 8; ++i) {
        int r = rowBase + ty * 8 + i;
        if (r >= M) continue;
        float4 o0, o1;
        unpack2(acc[i][0], o0.x, o0.y);
        unpack2(acc[i][1], o0.z, o0.w);
        unpack2(acc[i][2], o1.x, o1.y);
        unpack2(acc[i][3], o1.z, o1.w);
        float* cp = &C[(size_t)r * N + colBase + tx * 8];
        *(float4*)cp = o0;
        *(float4*)(cp + 4) = o1;
    }
}

// ---------------- layer-1 aggregation: warp per node, ALL 4 heads ----------------
// xlr layout: [node][512] = [xl(4h x 64) | xr(4h x 64)]. lane handles 8 channels,
// head = lane>>3; scores reduced within 8-lane groups; online softmax per head.
__global__ void agg1_kernel(const float* __restrict__ xlr, const float* __restrict__ att,
                            const float* __restrict__ bias, float* __restrict__ out)
{
    int node = blockIdx.x * (blockDim.x >> 5) + (threadIdx.x >> 5);
    if (node >= N_NODES) return;
    int lane = threadIdx.x & 31;
    int c0 = lane * 8;

    const float* xrp = xlr + (size_t)node * 512 + 256 + c0;
    float4 x0 = *(const float4*)xrp, x1 = *(const float4*)(xrp + 4);
    float4 t0 = *(const float4*)&att[c0], t1 = *(const float4*)&att[c0 + 4];
    float xrv[8] = {x0.x, x0.y, x0.z, x0.w, x1.x, x1.y, x1.z, x1.w};
    float atv[8] = {t0.x, t0.y, t0.z, t0.w, t1.x, t1.y, t1.z, t1.w};

    float m = -FLT_MAX, s = 0.f;
    float acc[8] = {0.f, 0.f, 0.f, 0.f, 0.f, 0.f, 0.f, 0.f};

    int e0 = g_rowptr[node], e1 = g_rowptr[node + 1];
    for (int e = e0; e < e1; ++e) {
        int src = g_srcs[e];
        const float* vp = xlr + (size_t)src * 512 + c0;
        float4 v0 = *(const float4*)vp, v1 = *(const float4*)(vp + 4);
        float v[8] = {v0.x, v0.y, v0.z, v0.w, v1.x, v1.y, v1.z, v1.w};
        float p = 0.f;
        #pragma unroll
        for (int i = 0; i < 8; ++i) {
            float t = v[i] + xrv[i];
            t = t > 0.f ? t : 0.2f * t;
            p += t * atv[i];
        }
        p += __shfl_xor_sync(0xffffffffu, p, 4);
        p += __shfl_xor_sync(0xffffffffu, p, 2);
        p += __shfl_xor_sync(0xffffffffu, p, 1);

        float nm = fmaxf(m, p);
        float c = __expf(m - nm);
        float w = __expf(p - nm);
        #pragma unroll
        for (int i = 0; i < 8; ++i) acc[i] = acc[i] * c + w * v[i];
        s = s * c + w;
        m = nm;
    }

    float inv = 1.f / s;
    float4 b0 = *(const float4*)&bias[c0], b1 = *(const float4*)&bias[c0 + 4];
    float bv[8] = {b0.x, b0.y, b0.z, b0.w, b1.x, b1.y, b1.z, b1.w};
    float o[8];
    #pragma unroll
    for (int i = 0; i < 8; ++i) o[i] = fmaxf(acc[i] * inv + bv[i], 0.f);
    float* op = out + (size_t)node * HC1 + c0;
    *(float4*)op       = make_float4(o[0], o[1], o[2], o[3]);
    *(float4*)(op + 4) = make_float4(o[4], o[5], o[6], o[7]);
}

// ---------------- layer-2 aggregation: warp per node, 1 head, C=64 ----------------
// xlr2 layout: [node][128] = [xl2(64) | xr2(64)]
__global__ void agg2_kernel(const float* __restrict__ xlr, const float* __restrict__ att,
                            const float* __restrict__ bias, float* __restrict__ out)
{
    int node = blockIdx.x * (blockDim.x >> 5) + (threadIdx.x >> 5);
    if (node >= N_NODES) return;
    int lane = threadIdx.x & 31;
    int c0 = lane * 2;

    float2 xrv = *(const float2*)&xlr[(size_t)node * 128 + 64 + c0];
    float2 atv = *(const float2*)&att[c0];

    float m = -FLT_MAX, s = 0.f, acc0 = 0.f, acc1 = 0.f;
    int e0 = g_rowptr[node], e1 = g_rowptr[node + 1];
    for (int e = e0; e < e1; ++e) {
        int src = g_srcs[e];
        float2 v = *(const float2*)&xlr[(size_t)src * 128 + c0];
        float t0 = v.x + xrv.x; t0 = t0 > 0.f ? t0 : 0.2f * t0;
        float t1 = v.y + xrv.y; t1 = t1 > 0.f ? t1 : 0.2f * t1;
        float p = t0 * atv.x + t1 * atv.y;
        #pragma unroll
        for (int o = 16; o; o >>= 1) p += __shfl_xor_sync(0xffffffffu, p, o);

        float nm = fmaxf(m, p);
        float c = __expf(m - nm);
        float w = __expf(p - nm);
        acc0 = acc0 * c + w * v.x;
        acc1 = acc1 * c + w * v.y;
        s = s * c + w;
        m = nm;
    }

    float inv = 1.f / s;
    float o0 = fmaxf(acc0 * inv + bias[c0],     0.f);
    float o1 = fmaxf(acc1 * inv + bias[c0 + 1], 0.f);
    *(float2*)&out[(size_t)node * C2 + c0] = make_float2(o0, o1);
}

// ---------------- final linear: out[N,10] = h2[N,64] @ Wlin[64,10] + blin ----------------
__global__ void final_kernel(const float* __restrict__ h, const float* __restrict__ W,
                             const float* __restrict__ b, float* __restrict__ out)
{
    __shared__ float Ws[64 * NCLS];
    __shared__ float bs[NCLS];
    int t = threadIdx.x;
    for (int i = t; i < 64 * NCLS; i += blockDim.x) Ws[i] = W[i];
    if (t < NCLS) bs[t] = b[t];
    __syncthreads();

    int row = blockIdx.x * blockDim.x + t;
    if (row >= N_NODES) return;

    float acc[NCLS];
    #pragma unroll
    for (int j = 0; j < NCLS; ++j) acc[j] = bs[j];
    const float* hr = &h[(size_t)row * 64];
    #pragma unroll
    for (int k = 0; k < 64; ++k) {
        float hv = hr[k];
        #pragma unroll
        for (int j = 0; j < NCLS; ++j) acc[j] += hv * Ws[k * NCLS + j];
    }
    #pragma unroll
    for (int j = 0; j < NCLS; ++j) out[(size_t)row * NCLS + j] = acc[j];
}

// ---------------- launch ----------------
static float* sym_f(const void* s) { void* p = nullptr; cudaGetSymbolAddress(&p, s); return (float*)p; }

extern "C" void kernel_launch(void* const* d_in, const int* in_sizes, int n_in,
                              void* d_out, int out_size)
{
    const float* x    = (const float*)d_in[0];
    const int*   ei   = (const int*)  d_in[1];
    const float* Wl1  = (const float*)d_in[2];
    const float* Wr1  = (const float*)d_in[3];
    const float* att1 = (const float*)d_in[4];
    const float* b1   = (const float*)d_in[5];
    const float* Wl2  = (const float*)d_in[6];
    const float* Wr2  = (const float*)d_in[7];
    const float* att2 = (const float*)d_in[8];
    const float* b2   = (const float*)d_in[9];
    const float* Wlin = (const float*)d_in[10];
    const float* blin = (const float*)d_in[11];
    float* out = (float*)d_out;

    float* xlr1 = sym_f(g_xlr1);
    float* h1   = sym_f(g_h1);
    float* xlr2 = sym_f(g_xlr2);
    float* h2   = sym_f(g_h2);
    float* Wp1  = sym_f(g_Wp1);
    float* Wp2  = sym_f(g_Wp2);

    const int EB = (E_TOT + 255) / 256;

    // weight packing (independent of everything else)
    packw_kernel<<<(IN_CH * 256 + 255) / 256, 256>>>(Wl1, Wr1, Wp1, IN_CH, 256);
    packw_kernel<<<(HC1 * 64 + 255) / 256, 256>>>(Wl2, Wr2, Wp2, HC1, 64);

    // CSR build (counts -> scan -> scatter)
    zero_cnt_kernel<<<NCHUNK, 256>>>();
    count_kernel<<<EB, 256>>>(ei);
    scan1_kernel<<<NCHUNK, 256>>>();
    scan2_kernel<<<1, 256>>>();
    scan3_kernel<<<NCHUNK, 256>>>();
    zero_cnt_kernel<<<NCHUNK, 256>>>();
    scatter_kernel<<<EB, 256>>>(ei);

    // Layer 1: one fused transform GEMM (N=512: xl | xr), then aggregation
    dim3 g1(512 / 128, (N_NODES + 127) / 128);
    gemm_f32x2_kernel<<<g1, 256>>>(x, Wp1, xlr1, N_NODES, 512, IN_CH);
    agg1_kernel<<<(N_NODES + 7) / 8, 256>>>(xlr1, att1, b1, h1);

    // Layer 2: one fused transform GEMM (N=128: xl | xr), then aggregation
    dim3 g2(1, (N_NODES + 127) / 128);
    gemm_f32x2_kernel<<<g2, 256>>>(h1, Wp2, xlr2, N_NODES, 128, HC1);
    agg2_kernel<<<(N_NODES + 7) / 8, 256>>>(xlr2, att2, b2, h2);

    // Classifier
    final_kernel<<<NCHUNK, 256>>>(h2, Wlin, blin, out);
}

// round 11
// speedup vs baseline: 1.0037x; 1.0007x over previous
#include <cuda_runtime.h>
#include <math.h>
#include <float.h>
#include <stdint.h>

#define N_NODES 50000
#define E_EDGES 800000
#define E_TOT   850000
#define IN_CH   256
#define H1      4
#define C_CH    64
#define HC1     256
#define C2      64
#define NCLS    10
#define NCHUNK  196         // ceil(50000/256)

// ---------------- scratch (device globals; no cudaMalloc allowed) ----------------
__device__ __align__(16) float g_xlr1[(size_t)N_NODES * 512];  // [xl1 | xr1]
__device__ __align__(16) float g_h1  [(size_t)N_NODES * HC1];
__device__ __align__(16) float g_xlr2[(size_t)N_NODES * 128];  // [xl2 | xr2]
__device__ __align__(16) float g_h2  [(size_t)N_NODES * C2];
__device__ __align__(16) float g_Wp1[(size_t)IN_CH * 512];     // [Wl1 | Wr1]
__device__ __align__(16) float g_Wp2[(size_t)HC1 * 128];       // [Wl2 | Wr2]
__device__ int g_rowptr[N_NODES + 1];
__device__ int g_cnt[N_NODES];
__device__ int g_srcs[E_TOT];
__device__ int g_bsum[256];
__device__ int g_boff[256];

// ---------------- f32x2 helpers ----------------
__device__ __forceinline__ unsigned long long pack2(float x, float y) {
    unsigned long long r;
    asm("mov.b64 %0, {%1, %2};" : "=l"(r) : "f"(x), "f"(y));
    return r;
}
__device__ __forceinline__ void unpack2(unsigned long long v, float& x, float& y) {
    asm("mov.b64 {%0, %1}, %2;" : "=f"(x), "=f"(y) : "l"(v));
}
__device__ __forceinline__ void ffma2(unsigned long long& d,
                                      unsigned long long a, unsigned long long b) {
    asm("fma.rn.f32x2 %0, %1, %2, %0;" : "+l"(d) : "l"(a), "l"(b));
}

// ---------------- CSR build ----------------
__global__ void zero_cnt_kernel() {
    int i = blockIdx.x * blockDim.x + threadIdx.x;
    if (i < N_NODES) g_cnt[i] = 0;
}
__global__ void count_kernel(const int* __restrict__ ei) {
    int i = blockIdx.x * blockDim.x + threadIdx.x;
    if (i >= E_TOT) return;
    int dst = (i < E_EDGES) ? ei[E_EDGES + i] : (i - E_EDGES);
    atomicAdd(&g_cnt[dst], 1);
}
__global__ void scan1_kernel() {
    __shared__ int sh[256];
    int t = threadIdx.x;
    int idx = blockIdx.x * 256 + t;
    int v = (idx < N_NODES) ? g_cnt[idx] : 0;
    sh[t] = v; __syncthreads();
    #pragma unroll
    for (int d = 1; d < 256; d <<= 1) {
        int x = (t >= d) ? sh[t - d] : 0;
        __syncthreads(); sh[t] += x; __syncthreads();
    }
    if (idx < N_NODES) g_rowptr[idx + 1] = sh[t];
    if (t == 255) g_bsum[blockIdx.x] = sh[255];
    if (idx == 0) g_rowptr[0] = 0;
}
__global__ void scan2_kernel() {
    __shared__ int sh[256];
    int t = threadIdx.x;
    int v = (t < NCHUNK) ? g_bsum[t] : 0;
    sh[t] = v; __syncthreads();
    #pragma unroll
    for (int d = 1; d < 256; d <<= 1) {
        int x = (t >= d) ? sh[t - d] : 0;
        __syncthreads(); sh[t] += x; __syncthreads();
    }
    g_boff[t] = sh[t] - v;
}
__global__ void scan3_kernel() {
    int idx = blockIdx.x * 256 + threadIdx.x;
    if (idx < N_NODES) g_rowptr[idx + 1] += g_boff[blockIdx.x];
}
__global__ void scatter_kernel(const int* __restrict__ ei) {
    int i = blockIdx.x * blockDim.x + threadIdx.x;
    if (i >= E_TOT) return;
    int src, dst;
    if (i < E_EDGES) { src = ei[i]; dst = ei[E_EDGES + i]; }
    else             { src = dst = i - E_EDGES; }
    int pos = g_rowptr[dst] + atomicAdd(&g_cnt[dst], 1);
    g_srcs[pos] = src;
}

// ---------------- weight packing: Wp[k][0..Nc-1]=Wa[k], [Nc..2Nc-1]=Wb[k] ----------------
__global__ void packw_kernel(const float* __restrict__ Wa, const float* __restrict__ Wb,
                             float* __restrict__ Wp, int K, int Nc) {
    int i = blockIdx.x * blockDim.x + threadIdx.x;
    if (i >= K * Nc) return;
    int k = i / Nc, c = i % Nc;
    Wp[(size_t)k * 2 * Nc + c]      = Wa[i];
    Wp[(size_t)k * 2 * Nc + Nc + c] = Wb[i];
}

// ---------------- fp32x2 GEMM: C[M,N] = A[M,K] @ B[K,N], BM=BN=128, BK=8 ----------------
__global__ void __launch_bounds__(256)
gemm_f32x2_kernel(const float* __restrict__ A, const float* __restrict__ B,
                  float* __restrict__ C, int M, int N, int K)
{
    const int BM = 128, BN = 128, BK = 8;
    __shared__ float As[2][BK][BM + 4];
    __shared__ float Bs[2][BK][BN];

    int tid = threadIdx.x;
    int rowBase = blockIdx.y * BM;
    int colBase = blockIdx.x * BN;

    int aRow = tid >> 1;            // 0..127
    int aCol = (tid & 1) * 4;       // 0 or 4
    int bRow = tid >> 5;            // 0..7
    int bCol = (tid & 31) * 4;      // 0..124
    int tx = tid & 15;              // 0..15
    int ty = tid >> 4;              // 0..15

    // prologue: load tile k0=0
    float4 aReg, bReg;
    {
        int r = rowBase + aRow;
        aReg = (r < M) ? *(const float4*)&A[(size_t)r * K + aCol]
                       : make_float4(0.f, 0.f, 0.f, 0.f);
        bReg = *(const float4*)&B[(size_t)bRow * N + colBase + bCol];
    }
    As[0][aCol + 0][aRow] = aReg.x;
    As[0][aCol + 1][aRow] = aReg.y;
    As[0][aCol + 2][aRow] = aReg.z;
    As[0][aCol + 3][aRow] = aReg.w;
    *(float4*)&Bs[0][bRow][bCol] = bReg;
    __syncthreads();

    unsigned long long acc[8][4];
    #pragma unroll
    for (int i = 0; i < 8; ++i)
        #pragma unroll
        for (int j = 0; j < 4; ++j) acc[i][j] = 0ull;

    int buf = 0;
    for (int k0 = 0; k0 < K; k0 += BK) {
        bool has_next = (k0 + BK < K);
        if (has_next) {
            int r = rowBase + aRow;
            aReg = (r < M) ? *(const float4*)&A[(size_t)r * K + k0 + BK + aCol]
                           : make_float4(0.f, 0.f, 0.f, 0.f);
            bReg = *(const float4*)&B[(size_t)(k0 + BK + bRow) * N + colBase + bCol];
        }
        #pragma unroll
        for (int k = 0; k < BK; ++k) {
            float4 a0 = *(const float4*)&As[buf][k][ty * 8];
            float4 a1 = *(const float4*)&As[buf][k][ty * 8 + 4];
            const unsigned long long* b64 =
                (const unsigned long long*)&Bs[buf][k][tx * 8];
            unsigned long long bb0 = b64[0], bb1 = b64[1], bb2 = b64[2], bb3 = b64[3];
            float av[8] = {a0.x, a0.y, a0.z, a0.w, a1.x, a1.y, a1.z, a1.w};
            #pragma unroll
            for (int i = 0; i < 8; ++i) {
                unsigned long long aa = pack2(av[i], av[i]);
                ffma2(acc[i][0], aa, bb0);
                ffma2(acc[i][1], aa, bb1);
                ffma2(acc[i][2], aa, bb2);
                ffma2(acc[i][3], aa, bb3);
            }
        }
        if (has_next) {
            buf ^= 1;
            As[buf][aCol + 0][aRow] = aReg.x;
            As[buf][aCol + 1][aRow] = aReg.y;
            As[buf][aCol + 2][aRow] = aReg.z;
            As[buf][aCol + 3][aRow] = aReg.w;
            *(float4*)&Bs[buf][bRow][bCol] = bReg;
            __syncthreads();
        }
    }

    #pragma unroll
    for (int i = 0; i < 8; ++i) {
        int r = rowBase + ty * 8 + i;
        if (r >= M) continue;
        float4 o0, o1;
        unpack2(acc[i][0], o0.x, o0.y);
        unpack2(acc[i][1], o0.z, o0.w);
        unpack2(acc[i][2], o1.x, o1.y);
        unpack2(acc[i][3], o1.z, o1.w);
        float* cp = &C[(size_t)r * N + colBase + tx * 8];
        *(float4*)cp = o0;
        *(float4*)(cp + 4) = o1;
    }
}

// ---------------- layer-1 aggregation: warp per node, ALL 4 heads ----------------
// xlr layout: [node][512] = [xl(4h x 64) | xr(4h x 64)]. lane handles 8 channels,
// head = lane>>3; scores reduced within 8-lane groups; online softmax per head.
__global__ void agg1_kernel(const float* __restrict__ xlr, const float* __restrict__ att,
                            const float* __restrict__ bias, float* __restrict__ out)
{
    int node = blockIdx.x * (blockDim.x >> 5) + (threadIdx.x >> 5);
    if (node >= N_NODES) return;
    int lane = threadIdx.x & 31;
    int c0 = lane * 8;

    const float* xrp = xlr + (size_t)node * 512 + 256 + c0;
    float4 x0 = *(const float4*)xrp, x1 = *(const float4*)(xrp + 4);
    float4 t0 = *(const float4*)&att[c0], t1 = *(const float4*)&att[c0 + 4];
    float xrv[8] = {x0.x, x0.y, x0.z, x0.w, x1.x, x1.y, x1.z, x1.w};
    float atv[8] = {t0.x, t0.y, t0.z, t0.w, t1.x, t1.y, t1.z, t1.w};

    float m = -FLT_MAX, s = 0.f;
    float acc[8] = {0.f, 0.f, 0.f, 0.f, 0.f, 0.f, 0.f, 0.f};

    int e0 = g_rowptr[node], e1 = g_rowptr[node + 1];
    for (int e = e0; e < e1; ++e) {
        int src = g_srcs[e];
        const float* vp = xlr + (size_t)src * 512 + c0;
        float4 v0 = *(const float4*)vp, v1 = *(const float4*)(vp + 4);
        float v[8] = {v0.x, v0.y, v0.z, v0.w, v1.x, v1.y, v1.z, v1.w};
        float p = 0.f;
        #pragma unroll
        for (int i = 0; i < 8; ++i) {
            float t = v[i] + xrv[i];
            t = t > 0.f ? t : 0.2f * t;
            p += t * atv[i];
        }
        p += __shfl_xor_sync(0xffffffffu, p, 4);
        p += __shfl_xor_sync(0xffffffffu, p, 2);
        p += __shfl_xor_sync(0xffffffffu, p, 1);

        float nm = fmaxf(m, p);
        float c = __expf(m - nm);
        float w = __expf(p - nm);
        #pragma unroll
        for (int i = 0; i < 8; ++i) acc[i] = acc[i] * c + w * v[i];
        s = s * c + w;
        m = nm;
    }

    float inv = 1.f / s;
    float4 b0 = *(const float4*)&bias[c0], b1 = *(const float4*)&bias[c0 + 4];
    float bv[8] = {b0.x, b0.y, b0.z, b0.w, b1.x, b1.y, b1.z, b1.w};
    float o[8];
    #pragma unroll
    for (int i = 0; i < 8; ++i) o[i] = fmaxf(acc[i] * inv + bv[i], 0.f);
    float* op = out + (size_t)node * HC1 + c0;
    *(float4*)op       = make_float4(o[0], o[1], o[2], o[3]);
    *(float4*)(op + 4) = make_float4(o[4], o[5], o[6], o[7]);
}

// ---------------- layer-2 aggregation: warp per node, 1 head, C=64 ----------------
// xlr2 layout: [node][128] = [xl2(64) | xr2(64)]
__global__ void agg2_kernel(const float* __restrict__ xlr, const float* __restrict__ att,
                            const float* __restrict__ bias, float* __restrict__ out)
{
    int node = blockIdx.x * (blockDim.x >> 5) + (threadIdx.x >> 5);
    if (node >= N_NODES) return;
    int lane = threadIdx.x & 31;
    int c0 = lane * 2;

    float2 xrv = *(const float2*)&xlr[(size_t)node * 128 + 64 + c0];
    float2 atv = *(const float2*)&att[c0];

    float m = -FLT_MAX, s = 0.f, acc0 = 0.f, acc1 = 0.f;
    int e0 = g_rowptr[node], e1 = g_rowptr[node + 1];
    for (int e = e0; e < e1; ++e) {
        int src = g_srcs[e];
        float2 v = *(const float2*)&xlr[(size_t)src * 128 + c0];
        float t0 = v.x + xrv.x; t0 = t0 > 0.f ? t0 : 0.2f * t0;
        float t1 = v.y + xrv.y; t1 = t1 > 0.f ? t1 : 0.2f * t1;
        float p = t0 * atv.x + t1 * atv.y;
        #pragma unroll
        for (int o = 16; o; o >>= 1) p += __shfl_xor_sync(0xffffffffu, p, o);

        float nm = fmaxf(m, p);
        float c = __expf(m - nm);
        float w = __expf(p - nm);
        acc0 = acc0 * c + w * v.x;
        acc1 = acc1 * c + w * v.y;
        s = s * c + w;
        m = nm;
    }

    float inv = 1.f / s;
    float o0 = fmaxf(acc0 * inv + bias[c0],     0.f);
    float o1 = fmaxf(acc1 * inv + bias[c0 + 1], 0.f);
    *(float2*)&out[(size_t)node * C2 + c0] = make_float2(o0, o1);
}

// ---------------- final linear: out[N,10] = h2[N,64] @ Wlin[64,10] + blin ----------------
__global__ void final_kernel(const float* __restrict__ h, const float* __restrict__ W,
                             const float* __restrict__ b, float* __restrict__ out)
{
    __shared__ float Ws[64 * NCLS];
    __shared__ float bs[NCLS];
    int t = threadIdx.x;
    for (int i = t; i < 64 * NCLS; i += blockDim.x) Ws[i] = W[i];
    if (t < NCLS) bs[t] = b[t];
    __syncthreads();

    int row = blockIdx.x * blockDim.x + t;
    if (row >= N_NODES) return;

    float acc[NCLS];
    #pragma unroll
    for (int j = 0; j < NCLS; ++j) acc[j] = bs[j];
    const float* hr = &h[(size_t)row * 64];
    #pragma unroll
    for (int k = 0; k < 64; ++k) {
        float hv = hr[k];
        #pragma unroll
        for (int j = 0; j < NCLS; ++j) acc[j] += hv * Ws[k * NCLS + j];
    }
    #pragma unroll
    for (int j = 0; j < NCLS; ++j) out[(size_t)row * NCLS + j] = acc[j];
}

// ---------------- launch ----------------
static float* sym_f(const void* s) { void* p = nullptr; cudaGetSymbolAddress(&p, s); return (float*)p; }

extern "C" void kernel_launch(void* const* d_in, const int* in_sizes, int n_in,
                              void* d_out, int out_size)
{
    const float* x    = (const float*)d_in[0];
    const int*   ei   = (const int*)  d_in[1];
    const float* Wl1  = (const float*)d_in[2];
    const float* Wr1  = (const float*)d_in[3];
    const float* att1 = (const float*)d_in[4];
    const float* b1   = (const float*)d_in[5];
    const float* Wl2  = (const float*)d_in[6];
    const float* Wr2  = (const float*)d_in[7];
    const float* att2 = (const float*)d_in[8];
    const float* b2   = (const float*)d_in[9];
    const float* Wlin = (const float*)d_in[10];
    const float* blin = (const float*)d_in[11];
    float* out = (float*)d_out;

    float* xlr1 = sym_f(g_xlr1);
    float* h1   = sym_f(g_h1);
    float* xlr2 = sym_f(g_xlr2);
    float* h2   = sym_f(g_h2);
    float* Wp1  = sym_f(g_Wp1);
    float* Wp2  = sym_f(g_Wp2);

    const int EB = (E_TOT + 255) / 256;

    // weight packing (independent of everything else)
    packw_kernel<<<(IN_CH * 256 + 255) / 256, 256>>>(Wl1, Wr1, Wp1, IN_CH, 256);
    packw_kernel<<<(HC1 * 64 + 255) / 256, 256>>>(Wl2, Wr2, Wp2, HC1, 64);

    // CSR build (counts -> scan -> scatter)
    zero_cnt_kernel<<<NCHUNK, 256>>>();
    count_kernel<<<EB, 256>>>(ei);
    scan1_kernel<<<NCHUNK, 256>>>();
    scan2_kernel<<<1, 256>>>();
    scan3_kernel<<<NCHUNK, 256>>>();
    zero_cnt_kernel<<<NCHUNK, 256>>>();
    scatter_kernel<<<EB, 256>>>(ei);

    // Layer 1: one fused transform GEMM (N=512: xl | xr), then aggregation
    dim3 g1(512 / 128, (N_NODES + 127) / 128);
    gemm_f32x2_kernel<<<g1, 256>>>(x, Wp1, xlr1, N_NODES, 512, IN_CH);
    agg1_kernel<<<(N_NODES + 7) / 8, 256>>>(xlr1, att1, b1, h1);

    // Layer 2: one fused transform GEMM (N=128: xl | xr), then aggregation
    dim3 g2(1, (N_NODES + 127) / 128);
    gemm_f32x2_kernel<<<g2, 256>>>(h1, Wp2, xlr2, N_NODES, 128, HC1);
    agg2_kernel<<<(N_NODES + 7) / 8, 256>>>(xlr2, att2, b2, h2);

    // Classifier
    final_kernel<<<NCHUNK, 256>>>(h2, Wlin, blin, out);
}